// round 14
// baseline (speedup 1.0000x reference)
#include <cuda_runtime.h>
#include <cstdint>

#define BN 128
#define TT 512
#define NR 512
#define NOUT 512
#define PM 4
#define PN 32
#define MB 32
#define NJ 16
#define NTH 256
#define DT_TAU 0.2f

typedef unsigned long long u64;

// ---------------- global scratch ---------------------------------------------
__device__ float g_h[BN * NR];
__device__ float g_rh[BN * NR];
__device__ unsigned g_cnt[PM];
__device__ volatile unsigned g_gen[PM];

// ---------------- f32x2 helpers ----------------------------------------------
__device__ __forceinline__ u64 ffma2(u64 a, u64 b, u64 c) {
    u64 d;
    asm("fma.rn.f32x2 %0, %1, %2, %3;" : "=l"(d) : "l"(a), "l"(b), "l"(c));
    return d;
}
__device__ __forceinline__ u64 addf2(u64 a, u64 b) {
    u64 d;
    asm("add.rn.f32x2 %0, %1, %2;" : "=l"(d) : "l"(a), "l"(b));
    return d;
}
__device__ __forceinline__ u64 pack2(float lo, float hi) {
    u64 d;
    asm("mov.b64 %0, {%1, %2};" : "=l"(d) : "f"(lo), "f"(hi));
    return d;
}
__device__ __forceinline__ float2 unpack2(u64 d) {
    float2 r;
    asm("mov.b64 {%0, %1}, %2;" : "=f"(r.x), "=f"(r.y) : "l"(d));
    return r;
}
__device__ __forceinline__ void cp16(unsigned dst, const void* src) {
    asm volatile("cp.async.cg.shared.global [%0], [%1], 16;"
                 :: "r"(dst), "l"(src) : "memory");
}
__device__ __forceinline__ void cp8(unsigned dst, const void* src) {
    asm volatile("cp.async.ca.shared.global [%0], [%1], 8;"
                 :: "r"(dst), "l"(src) : "memory");
}
#define CP_COMMIT() asm volatile("cp.async.commit_group;" ::: "memory")
#define CP_WAIT(N)  asm volatile("cp.async.wait_group %0;" :: "n"(N) : "memory")

// ---------------- SMEM layout -------------------------------------------------
#define WZR_OFF   0
#define WH_OFF    65536
#define HS_OFF    98304
#define HS_STRIDE 2064
#define XT_OFF    164352      // 2 x 256 B (t-parity double buffer)
#define XW_OFF    164864      // 6 x 16 floats
#define ZBUF_OFF  165376      // 32 x 16 u64
#define PART_OFF  169472      // 8 kq x 32 u x 8 u64 = 16 KB
#define SMEM_TOTAL 185856

// ---------------- split group barrier (atomic arrive / poll wait) -------------
__device__ __forceinline__ void bar_arrive(int g, unsigned tgt) {
    __syncthreads();
    if (threadIdx.x == 0) {
        __threadfence();
        unsigned old = atomicAdd(&g_cnt[g], 1u);
        if (old == tgt * (unsigned)PN - 1u) {
            __threadfence();
            g_gen[g] = tgt;
        }
    }
}
__device__ __forceinline__ void bar_wait(int g, unsigned tgt) {
    if (threadIdx.x == 0) {
        while (g_gen[g] < tgt) {}
        __threadfence();
    }
    __syncthreads();
}

__global__ void reset_bar_kernel() {
    int i = threadIdx.x;
    if (i < PM) { g_cnt[i] = 0u; g_gen[i] = 0u; }
}

// ---------------- staging: 16 rows x 512 floats -> HS half --------------------
__device__ __forceinline__ void stage_half(const float* __restrict__ src,
                                           unsigned smu, int rowbase,
                                           const float* __restrict__ xsrc,
                                           unsigned xtbuf, int b0, int t,
                                           bool do_x, int tid) {
    int row = rowbase + (tid >> 4), c0 = tid & 15;
    const float4* s = (const float4*)(src + (size_t)(b0 + row) * NR) + c0;
    unsigned d = smu + HS_OFF + row * HS_STRIDE + c0 * 16;
#pragma unroll
    for (int i = 0; i < 8; i++) cp16(d + i * 256, s + 16 * i);
    if (do_x && tid < 32)
        cp8(xtbuf + tid * 8, xsrc + ((size_t)(b0 + tid) * TT + t) * 2);
    CP_COMMIT();
}

// ---------------- p1 accumulate: 4 rows x 2 neurons x {z,r}, k sub-range ------
__device__ __forceinline__ void p1_acc(const char* smem, int rowbase, int kq,
                                       int rg, int n0, int n1, int i0, int i1,
                                       u64 aZ[4][2], u64 aR[4][2]) {
    const char* hb = smem + HS_OFF + (rowbase + 4 * rg) * HS_STRIDE;
    const ulonglong2* WZRu2 = (const ulonglong2*)(smem + WZR_OFF);
#pragma unroll 8
    for (int i = i0; i < i1; i++) {
        int k4 = 16 * kq + i;
        ulonglong2 h0v = *(const ulonglong2*)(hb + 0 * HS_STRIDE + k4 * 16);
        ulonglong2 h1v = *(const ulonglong2*)(hb + 1 * HS_STRIDE + k4 * 16);
        ulonglong2 h2v = *(const ulonglong2*)(hb + 2 * HS_STRIDE + k4 * 16);
        ulonglong2 h3v = *(const ulonglong2*)(hb + 3 * HS_STRIDE + k4 * 16);
        ulonglong2 wA0 = WZRu2[(2 * k4) * 16 + n0];
        ulonglong2 wA1 = WZRu2[(2 * k4) * 16 + n1];
        ulonglong2 wB0 = WZRu2[(2 * k4 + 1) * 16 + n0];
        ulonglong2 wB1 = WZRu2[(2 * k4 + 1) * 16 + n1];
        aZ[0][0] = ffma2(h0v.x, wA0.x, aZ[0][0]);
        aR[0][0] = ffma2(h0v.x, wA0.y, aR[0][0]);
        aZ[0][1] = ffma2(h0v.x, wA1.x, aZ[0][1]);
        aR[0][1] = ffma2(h0v.x, wA1.y, aR[0][1]);
        aZ[1][0] = ffma2(h1v.x, wA0.x, aZ[1][0]);
        aR[1][0] = ffma2(h1v.x, wA0.y, aR[1][0]);
        aZ[1][1] = ffma2(h1v.x, wA1.x, aZ[1][1]);
        aR[1][1] = ffma2(h1v.x, wA1.y, aR[1][1]);
        aZ[2][0] = ffma2(h2v.x, wA0.x, aZ[2][0]);
        aR[2][0] = ffma2(h2v.x, wA0.y, aR[2][0]);
        aZ[2][1] = ffma2(h2v.x, wA1.x, aZ[2][1]);
        aR[2][1] = ffma2(h2v.x, wA1.y, aR[2][1]);
        aZ[3][0] = ffma2(h3v.x, wA0.x, aZ[3][0]);
        aR[3][0] = ffma2(h3v.x, wA0.y, aR[3][0]);
        aZ[3][1] = ffma2(h3v.x, wA1.x, aZ[3][1]);
        aR[3][1] = ffma2(h3v.x, wA1.y, aR[3][1]);
        aZ[0][0] = ffma2(h0v.y, wB0.x, aZ[0][0]);
        aR[0][0] = ffma2(h0v.y, wB0.y, aR[0][0]);
        aZ[0][1] = ffma2(h0v.y, wB1.x, aZ[0][1]);
        aR[0][1] = ffma2(h0v.y, wB1.y, aR[0][1]);
        aZ[1][0] = ffma2(h1v.y, wB0.x, aZ[1][0]);
        aR[1][0] = ffma2(h1v.y, wB0.y, aR[1][0]);
        aZ[1][1] = ffma2(h1v.y, wB1.x, aZ[1][1]);
        aR[1][1] = ffma2(h1v.y, wB1.y, aR[1][1]);
        aZ[2][0] = ffma2(h2v.y, wB0.x, aZ[2][0]);
        aR[2][0] = ffma2(h2v.y, wB0.y, aR[2][0]);
        aZ[2][1] = ffma2(h2v.y, wB1.x, aZ[2][1]);
        aR[2][1] = ffma2(h2v.y, wB1.y, aR[2][1]);
        aZ[3][0] = ffma2(h3v.y, wB0.x, aZ[3][0]);
        aR[3][0] = ffma2(h3v.y, wB0.y, aR[3][0]);
        aZ[3][1] = ffma2(h3v.y, wB1.x, aZ[3][1]);
        aR[3][1] = ffma2(h3v.y, wB1.y, aR[3][1]);
    }
}

// ---------------- p2 accumulate: 4 rows x 2 neurons, k sub-range --------------
__device__ __forceinline__ void p2_acc(const char* smem, int rowbase, int kq,
                                       int rg, int jp, int i0, int i1,
                                       u64 acc[4][2]) {
    const char* hb = smem + HS_OFF + (rowbase + 4 * rg) * HS_STRIDE;
    const ulonglong2* WHu2 = (const ulonglong2*)(smem + WH_OFF);
#pragma unroll 8
    for (int i = i0; i < i1; i++) {
        int k4 = 16 * kq + i;
        ulonglong2 h0v = *(const ulonglong2*)(hb + 0 * HS_STRIDE + k4 * 16);
        ulonglong2 h1v = *(const ulonglong2*)(hb + 1 * HS_STRIDE + k4 * 16);
        ulonglong2 h2v = *(const ulonglong2*)(hb + 2 * HS_STRIDE + k4 * 16);
        ulonglong2 h3v = *(const ulonglong2*)(hb + 3 * HS_STRIDE + k4 * 16);
        ulonglong2 wA = WHu2[(2 * k4) * 8 + jp];
        ulonglong2 wB = WHu2[(2 * k4 + 1) * 8 + jp];
        acc[0][0] = ffma2(h0v.x, wA.x, acc[0][0]);
        acc[0][1] = ffma2(h0v.x, wA.y, acc[0][1]);
        acc[1][0] = ffma2(h1v.x, wA.x, acc[1][0]);
        acc[1][1] = ffma2(h1v.x, wA.y, acc[1][1]);
        acc[2][0] = ffma2(h2v.x, wA.x, acc[2][0]);
        acc[2][1] = ffma2(h2v.x, wA.y, acc[2][1]);
        acc[3][0] = ffma2(h3v.x, wA.x, acc[3][0]);
        acc[3][1] = ffma2(h3v.x, wA.y, acc[3][1]);
        acc[0][0] = ffma2(h0v.y, wB.x, acc[0][0]);
        acc[0][1] = ffma2(h0v.y, wB.y, acc[0][1]);
        acc[1][0] = ffma2(h1v.y, wB.x, acc[1][0]);
        acc[1][1] = ffma2(h1v.y, wB.y, acc[1][1]);
        acc[2][0] = ffma2(h2v.y, wB.x, acc[2][0]);
        acc[2][1] = ffma2(h2v.y, wB.y, acc[2][1]);
        acc[3][0] = ffma2(h3v.y, wB.x, acc[3][0]);
        acc[3][1] = ffma2(h3v.y, wB.y, acc[3][1]);
    }
}

// ---------------- persistent recurrent kernel ---------------------------------
__global__ void __launch_bounds__(NTH, 1)
rnn_persistent(const float* __restrict__ x, const float* __restrict__ init_state,
               const float* __restrict__ W_enc, const float* __restrict__ W_wz,
               const float* __restrict__ W_uz, const float* __restrict__ W_wr,
               const float* __restrict__ W_ur, const float* __restrict__ W_wh,
               const float* __restrict__ W_uh, float* __restrict__ out_h) {
    extern __shared__ char smem[];
    const int tid = threadIdx.x;
    const int gm = blockIdx.x & 3;
    const int gn = blockIdx.x >> 2;
    const int b0 = gm * MB;
    const int j0 = gn * NJ;
    const int kq = tid >> 5;          // k-eighth (warp-uniform)
    const int u  = tid & 31;
    const int jp = u & 7;
    const int rg = u >> 3;            // 0..3 (4 rows each within a half)
    const int n0 = 2 * jp, n1 = n0 + 1;
    const int erow = tid >> 4;        // epilogue row-in-half 0..15
    const int ec   = tid & 15;        // epilogue neuron 0..15
    const int euu  = (erow >> 2) * 8 + (ec >> 1);
    const int eii  = (erow & 3) * 2 + (ec & 1);
    const unsigned smu = (unsigned)__cvta_generic_to_shared(smem);
    unsigned ev = 0;

    ulonglong2* WZRu2 = (ulonglong2*)(smem + WZR_OFF);
    ulonglong2* WHu2  = (ulonglong2*)(smem + WH_OFF);
    float* wxz0 = (float*)(smem + XW_OFF);
    float* wxz1 = wxz0 + 16;
    float* wxr0 = wxz0 + 32;
    float* wxr1 = wxz0 + 48;
    float* wxh0 = wxz0 + 64;
    float* wxh1 = wxz0 + 80;
    u64*   ZBUF = (u64*)(smem + ZBUF_OFF);
    u64*   PART = (u64*)(smem + PART_OFF);
    float* PARTF = (float*)(smem + PART_OFF);

    // ---- prologue: stage init_state halves; W_enc into WH layout ----
    stage_half(init_state, smu, 0, x, 0, b0, 0, false, tid);
    stage_half(init_state, smu, 16, x, 0, b0, 0, false, tid);
    for (int idx = tid; idx < 2048; idx += NTH) {
        int p = idx & 255, q = idx >> 8;
        float2 a = *(const float2*)&W_enc[(size_t)(j0 + 2 * q) * NR + 2 * p];
        float2 b = *(const float2*)&W_enc[(size_t)(j0 + 2 * q + 1) * NR + 2 * p];
        WHu2[p * 8 + q] = make_ulonglong2(pack2(a.x, a.y), pack2(b.x, b.y));
    }
    CP_WAIT(0);
    __syncthreads();
    // h0 = init_state @ W_enc^T (two halves)
#pragma unroll
    for (int hf = 0; hf < 2; hf++) {
        int rb = 16 * hf;
        u64 acc[4][2];
#pragma unroll
        for (int r = 0; r < 4; r++) { acc[r][0] = 0ull; acc[r][1] = 0ull; }
        p2_acc(smem, rb, kq, rg, jp, 0, 16, acc);
#pragma unroll
        for (int r = 0; r < 4; r++)
#pragma unroll
            for (int n = 0; n < 2; n++) {
                float2 t2 = unpack2(acc[r][n]);
                PARTF[(kq * 32 + u) * 8 + r * 2 + n] = t2.x + t2.y;
            }
        __syncthreads();
        {
            float s = 0.f;
#pragma unroll
            for (int q = 0; q < 8; q++)
                s += PARTF[(q * 32 + euu) * 8 + eii];
            g_h[(size_t)(b0 + rb + erow) * NR + j0 + ec] = s;
        }
        __syncthreads();
    }

    // ---- stationary weights ----
    for (int idx = tid; idx < 4096; idx += NTH) {
        int p = idx & 255, jj = idx >> 8;
        float2 wz = *(const float2*)&W_uz[(size_t)(j0 + jj) * NR + 2 * p];
        float2 wr = *(const float2*)&W_ur[(size_t)(j0 + jj) * NR + 2 * p];
        WZRu2[p * 16 + jj] = make_ulonglong2(pack2(wz.x, wz.y), pack2(wr.x, wr.y));
    }
    for (int idx = tid; idx < 2048; idx += NTH) {
        int p = idx & 255, q = idx >> 8;
        float2 a = *(const float2*)&W_uh[(size_t)(j0 + 2 * q) * NR + 2 * p];
        float2 b = *(const float2*)&W_uh[(size_t)(j0 + 2 * q + 1) * NR + 2 * p];
        WHu2[p * 8 + q] = make_ulonglong2(pack2(a.x, a.y), pack2(b.x, b.y));
    }
    if (tid < 16) {
        wxz0[tid] = W_wz[(j0 + tid) * 2 + 0];
        wxz1[tid] = W_wz[(j0 + tid) * 2 + 1];
        wxr0[tid] = W_wr[(j0 + tid) * 2 + 0];
        wxr1[tid] = W_wr[(j0 + tid) * 2 + 1];
        wxh0[tid] = W_wh[(j0 + tid) * 2 + 0];
        wxh1[tid] = W_wh[(j0 + tid) * 2 + 1];
    }
    bar_arrive(gm, ++ev);
    bar_wait(gm, ev);
    stage_half(g_h, smu, 0, x, smu + XT_OFF, b0, 0, true, tid);   // h H0 (+x t=0)
    stage_half(g_h, smu, 16, x, 0, b0, 0, false, tid);            // h H1

    for (int t = 0; t < TT; t++) {
        const float2* xts = (const float2*)(smem + XT_OFF + (t & 1) * 256);
        unsigned xnext = smu + XT_OFF + ((t + 1) & 1) * 256;

        // ================ phase 1, half 0 ================
        CP_WAIT(1);               // h(H0) ready (h(H1) may be in flight)
        __syncthreads();
        {
            u64 aZ[4][2], aR[4][2];
#pragma unroll
            for (int r = 0; r < 4; r++) {
                aZ[r][0] = 0ull; aZ[r][1] = 0ull;
                aR[r][0] = 0ull; aR[r][1] = 0ull;
            }
            p1_acc(smem, 0, kq, rg, n0, n1, 0, 16, aZ, aR);
#pragma unroll
            for (int r = 0; r < 4; r++)
#pragma unroll
                for (int n = 0; n < 2; n++) {
                    float2 tz = unpack2(aZ[r][n]);
                    float2 tr = unpack2(aR[r][n]);
                    PART[(kq * 32 + u) * 8 + r * 2 + n] =
                        pack2(tz.x + tz.y, tr.x + tr.y);
                }
        }
        __syncthreads();
        {   // epilogue H0: z, r, rh
            u64 s = PART[(0 * 32 + euu) * 8 + eii];
#pragma unroll
            for (int q = 1; q < 8; q++)
                s = addf2(s, PART[(q * 32 + euu) * 8 + eii]);
            float2 zr = unpack2(s);
            float2 xt = xts[erow];
            float zp = zr.x + xt.x * wxz0[ec] + xt.y * wxz1[ec];
            float rp = zr.y + xt.x * wxr0[ec] + xt.y * wxr1[ec];
            float z = 1.f / (1.f + __expf(-zp));
            float r = 1.f / (1.f + __expf(-rp));
            float hown = *(const float*)(smem + HS_OFF + erow * HS_STRIDE +
                                         (size_t)(j0 + ec) * 4);
            ZBUF[erow * 16 + ec] = pack2(z, hown);
            g_rh[(size_t)(b0 + erow) * NR + j0 + ec] = r * hown;
        }
        bar_arrive(gm, ++ev);     // e1

        // ================ phase 1, half 1 (pipelined) ================
        CP_WAIT(0);               // h(H1) ready
        __syncthreads();
        {
            u64 aZ[4][2], aR[4][2];
#pragma unroll
            for (int r = 0; r < 4; r++) {
                aZ[r][0] = 0ull; aZ[r][1] = 0ull;
                aR[r][0] = 0ull; aR[r][1] = 0ull;
            }
            p1_acc(smem, 16, kq, rg, n0, n1, 0, 8, aZ, aR);
            bar_wait(gm, ev);                                      // e1 done
            stage_half(g_rh, smu, 0, x, 0, b0, 0, false, tid);     // rh H0
            p1_acc(smem, 16, kq, rg, n0, n1, 8, 16, aZ, aR);
#pragma unroll
            for (int r = 0; r < 4; r++)
#pragma unroll
                for (int n = 0; n < 2; n++) {
                    float2 tz = unpack2(aZ[r][n]);
                    float2 tr = unpack2(aR[r][n]);
                    PART[(kq * 32 + u) * 8 + r * 2 + n] =
                        pack2(tz.x + tz.y, tr.x + tr.y);
                }
        }
        __syncthreads();
        {   // epilogue H1
            u64 s = PART[(0 * 32 + euu) * 8 + eii];
#pragma unroll
            for (int q = 1; q < 8; q++)
                s = addf2(s, PART[(q * 32 + euu) * 8 + eii]);
            float2 zr = unpack2(s);
            float2 xt = xts[16 + erow];
            float zp = zr.x + xt.x * wxz0[ec] + xt.y * wxz1[ec];
            float rp = zr.y + xt.x * wxr0[ec] + xt.y * wxr1[ec];
            float z = 1.f / (1.f + __expf(-zp));
            float r = 1.f / (1.f + __expf(-rp));
            float hown = *(const float*)(smem + HS_OFF + (16 + erow) * HS_STRIDE +
                                         (size_t)(j0 + ec) * 4);
            ZBUF[(16 + erow) * 16 + ec] = pack2(z, hown);
            g_rh[(size_t)(b0 + 16 + erow) * NR + j0 + ec] = r * hown;
        }
        bar_arrive(gm, ++ev);     // e2

        // ================ phase 2, half 0 ================
        CP_WAIT(0);               // rh(H0) ready
        __syncthreads();
        {
            u64 acc[4][2];
#pragma unroll
            for (int r = 0; r < 4; r++) { acc[r][0] = 0ull; acc[r][1] = 0ull; }
            p2_acc(smem, 0, kq, rg, jp, 0, 8, acc);
            bar_wait(gm, ev);                                      // e2 done
            stage_half(g_rh, smu, 16, x, 0, b0, 0, false, tid);    // rh H1
            p2_acc(smem, 0, kq, rg, jp, 8, 16, acc);
#pragma unroll
            for (int r = 0; r < 4; r++)
#pragma unroll
                for (int n = 0; n < 2; n++) {
                    float2 t2 = unpack2(acc[r][n]);
                    PARTF[(kq * 32 + u) * 8 + r * 2 + n] = t2.x + t2.y;
                }
        }
        __syncthreads();
        {   // epilogue H0: u, tanh, h update
            float s = 0.f;
#pragma unroll
            for (int q = 0; q < 8; q++)
                s += PARTF[(q * 32 + euu) * 8 + eii];
            float2 xt = xts[erow];
            float up = s + xt.x * wxh0[ec] + xt.y * wxh1[ec];
            float th = tanhf(up);
            float2 zh = unpack2(ZBUF[erow * 16 + ec]);
            float hn = zh.y + DT_TAU * (zh.x - 1.f) * (zh.y - th);
            g_h[(size_t)(b0 + erow) * NR + j0 + ec] = hn;
            out_h[((size_t)(b0 + erow) * TT + t) * NR + j0 + ec] = hn;
        }
        bar_arrive(gm, ++ev);     // e3

        // ================ phase 2, half 1 ================
        CP_WAIT(0);               // rh(H1) ready
        __syncthreads();
        {
            u64 acc[4][2];
#pragma unroll
            for (int r = 0; r < 4; r++) { acc[r][0] = 0ull; acc[r][1] = 0ull; }
            p2_acc(smem, 16, kq, rg, jp, 0, 8, acc);
            bar_wait(gm, ev);                                      // e3 done
            stage_half(g_h, smu, 0, x, xnext, b0, t + 1,
                       t + 1 < TT, tid);                           // h' H0 (+x)
            p2_acc(smem, 16, kq, rg, jp, 8, 16, acc);
#pragma unroll
            for (int r = 0; r < 4; r++)
#pragma unroll
                for (int n = 0; n < 2; n++) {
                    float2 t2 = unpack2(acc[r][n]);
                    PARTF[(kq * 32 + u) * 8 + r * 2 + n] = t2.x + t2.y;
                }
        }
        __syncthreads();
        {   // epilogue H1
            float s = 0.f;
#pragma unroll
            for (int q = 0; q < 8; q++)
                s += PARTF[(q * 32 + euu) * 8 + eii];
            float2 xt = xts[16 + erow];
            float up = s + xt.x * wxh0[ec] + xt.y * wxh1[ec];
            float th = tanhf(up);
            float2 zh = unpack2(ZBUF[(16 + erow) * 16 + ec]);
            float hn = zh.y + DT_TAU * (zh.x - 1.f) * (zh.y - th);
            g_h[(size_t)(b0 + 16 + erow) * NR + j0 + ec] = hn;
            out_h[((size_t)(b0 + 16 + erow) * TT + t) * NR + j0 + ec] = hn;
        }
        bar_arrive(gm, ++ev);     // e4
        bar_wait(gm, ev);
        stage_half(g_h, smu, 16, x, 0, b0, 0, false, tid);         // h' H1
    }
    CP_WAIT(0);
    __syncthreads();
}

// ---------------- decoder: y = h @ W_dec^T  (f32x2 tiled GEMM) ----------------
__global__ void __launch_bounds__(256)
decoder_kernel(const float* __restrict__ h, const float* __restrict__ W,
               float* __restrict__ y) {
    __shared__ float HT[32 * 132];
    __shared__ float WT[32 * 68];
    const int tid = threadIdx.x;
    const int bt0 = blockIdx.x * 128;
    const int o0  = blockIdx.y * 64;
    const int rg = tid & 15;
    const int cg = tid >> 4;
    const int col0 = cg * 4;
    const int lrow = tid >> 1, lkh = (tid & 1) * 16;
    const int lcol = tid >> 2, lkw = (tid & 3) * 8;

    u64 acc[4][4];
#pragma unroll
    for (int i = 0; i < 4; i++)
#pragma unroll
        for (int c = 0; c < 4; c++) acc[i][c] = 0ull;

    for (int k0 = 0; k0 < NR; k0 += 32) {
        __syncthreads();
        const float4* hsrc =
            (const float4*)(h + (size_t)(bt0 + lrow) * NR + k0 + lkh);
#pragma unroll
        for (int j = 0; j < 4; j++) {
            float4 v = hsrc[j];
            int kk = lkh + 4 * j;
            HT[(kk + 0) * 132 + lrow] = v.x;
            HT[(kk + 1) * 132 + lrow] = v.y;
            HT[(kk + 2) * 132 + lrow] = v.z;
            HT[(kk + 3) * 132 + lrow] = v.w;
        }
        const float4* wsrc =
            (const float4*)(W + (size_t)(o0 + lcol) * NR + k0 + lkw);
#pragma unroll
        for (int j = 0; j < 2; j++) {
            float4 v = wsrc[j];
            int kk = lkw + 4 * j;
            WT[(kk + 0) * 68 + lcol] = v.x;
            WT[(kk + 1) * 68 + lcol] = v.y;
            WT[(kk + 2) * 68 + lcol] = v.z;
            WT[(kk + 3) * 68 + lcol] = v.w;
        }
        __syncthreads();
#pragma unroll 4
        for (int k = 0; k < 32; k++) {
            const u64* HTd = (const u64*)(HT + k * 132);
            u64 h0 = HTd[rg];
            u64 h1 = HTd[rg + 16];
            u64 h2 = HTd[rg + 32];
            u64 h3 = HTd[rg + 48];
            float4 wv = *(const float4*)(WT + k * 68 + col0);
            u64 w0 = pack2(wv.x, wv.x);
            u64 w1 = pack2(wv.y, wv.y);
            u64 w2 = pack2(wv.z, wv.z);
            u64 w3 = pack2(wv.w, wv.w);
            acc[0][0] = ffma2(h0, w0, acc[0][0]);
            acc[0][1] = ffma2(h0, w1, acc[0][1]);
            acc[0][2] = ffma2(h0, w2, acc[0][2]);
            acc[0][3] = ffma2(h0, w3, acc[0][3]);
            acc[1][0] = ffma2(h1, w0, acc[1][0]);
            acc[1][1] = ffma2(h1, w1, acc[1][1]);
            acc[1][2] = ffma2(h1, w2, acc[1][2]);
            acc[1][3] = ffma2(h1, w3, acc[1][3]);
            acc[2][0] = ffma2(h2, w0, acc[2][0]);
            acc[2][1] = ffma2(h2, w1, acc[2][1]);
            acc[2][2] = ffma2(h2, w2, acc[2][2]);
            acc[2][3] = ffma2(h2, w3, acc[2][3]);
            acc[3][0] = ffma2(h3, w0, acc[3][0]);
            acc[3][1] = ffma2(h3, w1, acc[3][1]);
            acc[3][2] = ffma2(h3, w2, acc[3][2]);
            acc[3][3] = ffma2(h3, w3, acc[3][3]);
        }
    }
#pragma unroll
    for (int i = 0; i < 4; i++) {
        int r = 2 * rg + 32 * i;
        float2 p0 = unpack2(acc[i][0]);
        float2 p1 = unpack2(acc[i][1]);
        float2 p2 = unpack2(acc[i][2]);
        float2 p3 = unpack2(acc[i][3]);
        float4 ra = make_float4(p0.x, p1.x, p2.x, p3.x);
        float4 rb = make_float4(p0.y, p1.y, p2.y, p3.y);
        *(float4*)(y + (size_t)(bt0 + r) * NOUT + o0 + col0) = ra;
        *(float4*)(y + (size_t)(bt0 + r + 1) * NOUT + o0 + col0) = rb;
    }
}

// ---------------- launch -------------------------------------------------------
extern "C" void kernel_launch(void* const* d_in, const int* in_sizes, int n_in,
                              void* d_out, int out_size) {
    const float* x          = (const float*)d_in[0];
    const float* init_state = (const float*)d_in[1];
    const float* W_enc      = (const float*)d_in[2];
    const float* W_wz       = (const float*)d_in[3];
    const float* W_uz       = (const float*)d_in[4];
    const float* W_wr       = (const float*)d_in[5];
    const float* W_ur       = (const float*)d_in[6];
    const float* W_wh       = (const float*)d_in[7];
    const float* W_uh       = (const float*)d_in[8];
    const float* W_dec      = (const float*)d_in[9];
    float* out = (float*)d_out;

    cudaFuncSetAttribute(rnn_persistent,
                         cudaFuncAttributeMaxDynamicSharedMemorySize, SMEM_TOTAL);

    rnn_persistent<<<PM * PN, NTH, SMEM_TOTAL>>>(
        x, init_state, W_enc, W_wz, W_uz, W_wr, W_ur, W_wh, W_uh, out);

    size_t hN = (size_t)BN * TT * NR;
    if ((size_t)out_size >= 2 * hN) {
        dim3 grid((BN * TT) / 128, NOUT / 64);
        decoder_kernel<<<grid, 256>>>(out, W_dec, out + hN);
    }

    reset_bar_kernel<<<1, 32>>>();
}

// round 15
// speedup vs baseline: 1.3801x; 1.3801x over previous
#include <cuda_runtime.h>
#include <cstdint>

#define BN 128
#define TT 512
#define NR 512
#define NOUT 512
#define PM 4
#define PN 32
#define MB 32
#define NJ 16
#define NTH 256
#define DT_TAU 0.2f

typedef unsigned long long u64;

// ---------------- global scratch ---------------------------------------------
__device__ float g_h[BN * NR];
__device__ float g_rh[BN * NR];
__device__ unsigned g_cnt[PM];
__device__ volatile unsigned g_gen[PM];

// ---------------- f32x2 helpers ----------------------------------------------
__device__ __forceinline__ u64 ffma2(u64 a, u64 b, u64 c) {
    u64 d;
    asm("fma.rn.f32x2 %0, %1, %2, %3;" : "=l"(d) : "l"(a), "l"(b), "l"(c));
    return d;
}
__device__ __forceinline__ u64 addf2(u64 a, u64 b) {
    u64 d;
    asm("add.rn.f32x2 %0, %1, %2;" : "=l"(d) : "l"(a), "l"(b));
    return d;
}
__device__ __forceinline__ u64 pack2(float lo, float hi) {
    u64 d;
    asm("mov.b64 %0, {%1, %2};" : "=l"(d) : "f"(lo), "f"(hi));
    return d;
}
__device__ __forceinline__ float2 unpack2(u64 d) {
    float2 r;
    asm("mov.b64 {%0, %1}, %2;" : "=f"(r.x), "=f"(r.y) : "l"(d));
    return r;
}
__device__ __forceinline__ void cp16(unsigned dst, const void* src) {
    asm volatile("cp.async.cg.shared.global [%0], [%1], 16;"
                 :: "r"(dst), "l"(src) : "memory");
}
__device__ __forceinline__ void cp8(unsigned dst, const void* src) {
    asm volatile("cp.async.ca.shared.global [%0], [%1], 8;"
                 :: "r"(dst), "l"(src) : "memory");
}
#define CP_COMMIT() asm volatile("cp.async.commit_group;" ::: "memory")
#define CP_WAIT0()  asm volatile("cp.async.wait_group 0;" ::: "memory")

// ---------------- SMEM layout -------------------------------------------------
// WZR : [kpair p][neuron jj] ull2 {z(k0,k1), r(k0,k1)} : 256*16*16 = 65536
// WH  : [kpair p][npair q]   ull2                      : 256*8*16  = 32768
// HS  : 32 rows x (512 f + 16B pad)                    : 66048
// XT/XW/ZBUF; PART: 8kq x 32u x 17 u64 (stride-padded) : 34816
#define WZR_OFF   0
#define WH_OFF    65536
#define HS_OFF    98304
#define HS_STRIDE 2064
#define XT_OFF    164352
#define XW_OFF    164608
#define ZBUF_OFF  164992
#define PART_OFF  169088
#define PART_STRIDE 17
#define SMEM_TOTAL (PART_OFF + 8 * 32 * PART_STRIDE * 8)   // 203904

// ---------------- group barrier (proven R5/R13 version) -----------------------
__device__ __forceinline__ void group_barrier(int g, unsigned& idx) {
    __syncthreads();
    if (threadIdx.x == 0) {
        __threadfence();
        unsigned old = atomicAdd(&g_cnt[g], 1u);
        if (old == idx * (unsigned)PN + (PN - 1)) {
            __threadfence();
            g_gen[g] = idx + 1u;
        } else {
            while (g_gen[g] < idx + 1u) {}
            __threadfence();
        }
    }
    __syncthreads();
    idx++;
}

__global__ void reset_bar_kernel() {
    int i = threadIdx.x;
    if (i < PM) { g_cnt[i] = 0u; g_gen[i] = 0u; }
}

// ---------------- async staging: 32 rows x 512 floats -> HS -------------------
__device__ __forceinline__ void issue_stage(const float* __restrict__ src,
                                            unsigned hs_u32,
                                            const float* __restrict__ xsrc,
                                            unsigned xt_u32, int b0, int t,
                                            bool do_x, int tid) {
    int row = tid >> 3, c0 = tid & 7;
    const float4* s = (const float4*)(src + (size_t)(b0 + row) * NR) + c0;
    unsigned d = hs_u32 + row * HS_STRIDE + c0 * 16;
#pragma unroll
    for (int i = 0; i < 16; i++) cp16(d + i * 128, s + 8 * i);
    if (do_x && tid < 32)
        cp8(xt_u32 + tid * 8, xsrc + ((size_t)(b0 + tid) * TT + t) * 2);
    CP_COMMIT();
}

// ---------------- p2-style dot: acc[2 grp][4 rows][2 n], 16 k4 per thread -----
__device__ __forceinline__ void p2_acc8(const char* smem, int rg, int jp,
                                        int kq, u64 acc[2][4][2]) {
    const char* hbA = smem + HS_OFF + 4 * rg * HS_STRIDE;
    const ulonglong2* WHu2 = (const ulonglong2*)(smem + WH_OFF);
#pragma unroll 4
    for (int i = 0; i < 16; i++) {
        int k4 = 16 * kq + i;
        ulonglong2 wA = WHu2[(2 * k4) * 8 + jp];
        ulonglong2 wB = WHu2[(2 * k4 + 1) * 8 + jp];
#pragma unroll
        for (int g = 0; g < 2; g++) {
            const char* hb = hbA + g * 16 * HS_STRIDE;
#pragma unroll
            for (int r = 0; r < 4; r++) {
                ulonglong2 hv =
                    *(const ulonglong2*)(hb + r * HS_STRIDE + k4 * 16);
                acc[g][r][0] = ffma2(hv.x, wA.x, acc[g][r][0]);
                acc[g][r][1] = ffma2(hv.x, wA.y, acc[g][r][1]);
                acc[g][r][0] = ffma2(hv.y, wB.x, acc[g][r][0]);
                acc[g][r][1] = ffma2(hv.y, wB.y, acc[g][r][1]);
            }
        }
    }
}

// ---------------- persistent recurrent kernel ---------------------------------
__global__ void __launch_bounds__(NTH, 1)
rnn_persistent(const float* __restrict__ x, const float* __restrict__ init_state,
               const float* __restrict__ W_enc, const float* __restrict__ W_wz,
               const float* __restrict__ W_uz, const float* __restrict__ W_wr,
               const float* __restrict__ W_ur, const float* __restrict__ W_wh,
               const float* __restrict__ W_uh, float* __restrict__ out_h) {
    extern __shared__ char smem[];
    const int tid = threadIdx.x;
    const int gm = blockIdx.x & 3;
    const int gn = blockIdx.x >> 2;
    const int b0 = gm * MB;
    const int j0 = gn * NJ;
    const int kq = tid >> 5;        // k-eighth (warp-uniform)
    const int u  = tid & 31;
    const int jp = u & 7;           // neuron pair
    const int rg = u >> 3;          // row group base (rows 4rg+.., +16)
    const int n0 = 2 * jp, n1 = n0 + 1;
    const unsigned smu = (unsigned)__cvta_generic_to_shared(smem);
    unsigned bidx = 0;

    ulonglong2* WZRu2 = (ulonglong2*)(smem + WZR_OFF);
    ulonglong2* WHu2  = (ulonglong2*)(smem + WH_OFF);
    float* wxz0 = (float*)(smem + XW_OFF);
    float* wxz1 = wxz0 + 16;
    float* wxr0 = wxz0 + 32;
    float* wxr1 = wxz0 + 48;
    float* wxh0 = wxz0 + 64;
    float* wxh1 = wxz0 + 80;
    u64*   ZBUF = (u64*)(smem + ZBUF_OFF);
    u64*   PART = (u64*)(smem + PART_OFF);
    float* PARTF = (float*)(smem + PART_OFF);
    float2* xts = (float2*)(smem + XT_OFF);
    const int pbase = (kq * 32 + u) * PART_STRIDE;      // u64 units
    const int pbasef = (kq * 32 + u) * (2 * PART_STRIDE); // float units

    // ---- prologue: stage init_state; W_enc into WH layout ----
    issue_stage(init_state, smu + HS_OFF, x, smu + XT_OFF, b0, 0, false, tid);
    for (int idx = tid; idx < 2048; idx += NTH) {
        int p = idx & 255, q = idx >> 8;
        float2 a = *(const float2*)&W_enc[(size_t)(j0 + 2 * q) * NR + 2 * p];
        float2 b = *(const float2*)&W_enc[(size_t)(j0 + 2 * q + 1) * NR + 2 * p];
        WHu2[p * 8 + q] = make_ulonglong2(pack2(a.x, a.y), pack2(b.x, b.y));
    }
    CP_WAIT0();
    __syncthreads();
    {   // h0 = init_state @ W_enc^T
        u64 acc[2][4][2];
#pragma unroll
        for (int g = 0; g < 2; g++)
#pragma unroll
            for (int r = 0; r < 4; r++) { acc[g][r][0] = 0ull; acc[g][r][1] = 0ull; }
        p2_acc8(smem, rg, jp, kq, acc);
#pragma unroll
        for (int g = 0; g < 2; g++)
#pragma unroll
            for (int r = 0; r < 4; r++)
#pragma unroll
                for (int n = 0; n < 2; n++) {
                    float2 t2 = unpack2(acc[g][r][n]);
                    PARTF[pbasef + g * 8 + r * 2 + n] = t2.x + t2.y;
                }
    }
    __syncthreads();
#pragma unroll
    for (int it = 0; it < 2; it++) {
        int j = 2 * tid + it;
        int row = j >> 4, c = j & 15;
        int uu = ((row >> 2) & 3) * 8 + (c >> 1);
        int slot = (row >> 4) * 8 + (row & 3) * 2 + (c & 1);
        float s = 0.f;
#pragma unroll
        for (int q = 0; q < 8; q++)
            s += PARTF[(q * 32 + uu) * (2 * PART_STRIDE) + slot];
        g_h[(size_t)(b0 + row) * NR + j0 + c] = s;
    }
    __syncthreads();

    // ---- stationary weights ----
    for (int idx = tid; idx < 4096; idx += NTH) {
        int p = idx & 255, jj = idx >> 8;
        float2 wz = *(const float2*)&W_uz[(size_t)(j0 + jj) * NR + 2 * p];
        float2 wr = *(const float2*)&W_ur[(size_t)(j0 + jj) * NR + 2 * p];
        WZRu2[p * 16 + jj] = make_ulonglong2(pack2(wz.x, wz.y), pack2(wr.x, wr.y));
    }
    for (int idx = tid; idx < 2048; idx += NTH) {
        int p = idx & 255, q = idx >> 8;
        float2 a = *(const float2*)&W_uh[(size_t)(j0 + 2 * q) * NR + 2 * p];
        float2 b = *(const float2*)&W_uh[(size_t)(j0 + 2 * q + 1) * NR + 2 * p];
        WHu2[p * 8 + q] = make_ulonglong2(pack2(a.x, a.y), pack2(b.x, b.y));
    }
    if (tid < 16) {
        wxz0[tid] = W_wz[(j0 + tid) * 2 + 0];
        wxz1[tid] = W_wz[(j0 + tid) * 2 + 1];
        wxr0[tid] = W_wr[(j0 + tid) * 2 + 0];
        wxr1[tid] = W_wr[(j0 + tid) * 2 + 1];
        wxh0[tid] = W_wh[(j0 + tid) * 2 + 0];
        wxh1[tid] = W_wh[(j0 + tid) * 2 + 1];
    }
    group_barrier(gm, bidx);  // h0 visible group-wide
    issue_stage(g_h, smu + HS_OFF, x, smu + XT_OFF, b0, 0, true, tid);

    for (int t = 0; t < TT; t++) {
        // ---------------- phase 1: z, r, r*h ----------------
        CP_WAIT0();
        __syncthreads();
        {
            u64 aZ[2][4][2], aR[2][4][2];
#pragma unroll
            for (int g = 0; g < 2; g++)
#pragma unroll
                for (int r = 0; r < 4; r++) {
                    aZ[g][r][0] = 0ull; aZ[g][r][1] = 0ull;
                    aR[g][r][0] = 0ull; aR[g][r][1] = 0ull;
                }
            const char* hbA = smem + HS_OFF + 4 * rg * HS_STRIDE;
#pragma unroll 2
            for (int i = 0; i < 16; i++) {
                int k4 = 16 * kq + i;
                ulonglong2 wA0 = WZRu2[(2 * k4) * 16 + n0];
                ulonglong2 wA1 = WZRu2[(2 * k4) * 16 + n1];
                ulonglong2 wB0 = WZRu2[(2 * k4 + 1) * 16 + n0];
                ulonglong2 wB1 = WZRu2[(2 * k4 + 1) * 16 + n1];
#pragma unroll
                for (int g = 0; g < 2; g++) {
                    const char* hb = hbA + g * 16 * HS_STRIDE;
#pragma unroll
                    for (int r = 0; r < 4; r++) {
                        ulonglong2 hv =
                            *(const ulonglong2*)(hb + r * HS_STRIDE + k4 * 16);
                        aZ[g][r][0] = ffma2(hv.x, wA0.x, aZ[g][r][0]);
                        aR[g][r][0] = ffma2(hv.x, wA0.y, aR[g][r][0]);
                        aZ[g][r][1] = ffma2(hv.x, wA1.x, aZ[g][r][1]);
                        aR[g][r][1] = ffma2(hv.x, wA1.y, aR[g][r][1]);
                        aZ[g][r][0] = ffma2(hv.y, wB0.x, aZ[g][r][0]);
                        aR[g][r][0] = ffma2(hv.y, wB0.y, aR[g][r][0]);
                        aZ[g][r][1] = ffma2(hv.y, wB1.x, aZ[g][r][1]);
                        aR[g][r][1] = ffma2(hv.y, wB1.y, aR[g][r][1]);
                    }
                }
            }
#pragma unroll
            for (int g = 0; g < 2; g++)
#pragma unroll
                for (int r = 0; r < 4; r++)
#pragma unroll
                    for (int n = 0; n < 2; n++) {
                        float2 tz = unpack2(aZ[g][r][n]);
                        float2 tr = unpack2(aR[g][r][n]);
                        PART[pbase + g * 8 + r * 2 + n] =
                            pack2(tz.x + tz.y, tr.x + tr.y);
                    }
        }
        __syncthreads();
#pragma unroll
        for (int it = 0; it < 2; it++) {
            int j = 2 * tid + it;
            int row = j >> 4, c = j & 15;
            int uu = ((row >> 2) & 3) * 8 + (c >> 1);
            int slot = (row >> 4) * 8 + (row & 3) * 2 + (c & 1);
            u64 s = PART[uu * PART_STRIDE + slot];
#pragma unroll
            for (int q = 1; q < 8; q++)
                s = addf2(s, PART[(q * 32 + uu) * PART_STRIDE + slot]);
            float2 zr = unpack2(s);
            float2 xt = xts[row];
            float zp = zr.x + xt.x * wxz0[c] + xt.y * wxz1[c];
            float rp = zr.y + xt.x * wxr0[c] + xt.y * wxr1[c];
            float z = 1.f / (1.f + __expf(-zp));
            float r = 1.f / (1.f + __expf(-rp));
            float hown = *(const float*)(smem + HS_OFF + row * HS_STRIDE +
                                         (size_t)(j0 + c) * 4);
            ZBUF[row * 16 + c] = pack2(z, hown);
            g_rh[(size_t)(b0 + row) * NR + j0 + c] = r * hown;
        }

        group_barrier(gm, bidx);  // rh visible group-wide
        issue_stage(g_rh, smu + HS_OFF, x, smu + XT_OFF, b0, 0, false, tid);

        // ---------------- phase 2: u, tanh, h update ----------------
        CP_WAIT0();
        __syncthreads();
        {
            u64 acc[2][4][2];
#pragma unroll
            for (int g = 0; g < 2; g++)
#pragma unroll
                for (int r = 0; r < 4; r++) { acc[g][r][0] = 0ull; acc[g][r][1] = 0ull; }
            p2_acc8(smem, rg, jp, kq, acc);
#pragma unroll
            for (int g = 0; g < 2; g++)
#pragma unroll
                for (int r = 0; r < 4; r++)
#pragma unroll
                    for (int n = 0; n < 2; n++) {
                        float2 t2 = unpack2(acc[g][r][n]);
                        PARTF[pbasef + g * 8 + r * 2 + n] = t2.x + t2.y;
                    }
        }
        __syncthreads();
#pragma unroll
        for (int it = 0; it < 2; it++) {
            int j = 2 * tid + it;
            int row = j >> 4, c = j & 15;
            int uu = ((row >> 2) & 3) * 8 + (c >> 1);
            int slot = (row >> 4) * 8 + (row & 3) * 2 + (c & 1);
            float s = 0.f;
#pragma unroll
            for (int q = 0; q < 8; q++)
                s += PARTF[(q * 32 + uu) * (2 * PART_STRIDE) + slot];
            float2 xt = xts[row];
            float up = s + xt.x * wxh0[c] + xt.y * wxh1[c];
            float th = tanhf(up);
            float2 zh = unpack2(ZBUF[row * 16 + c]);
            float hn = zh.y + DT_TAU * (zh.x - 1.f) * (zh.y - th);
            g_h[(size_t)(b0 + row) * NR + j0 + c] = hn;
            out_h[((size_t)(b0 + row) * TT + t) * NR + j0 + c] = hn;
        }

        group_barrier(gm, bidx);  // h(t+1) visible group-wide
        if (t + 1 < TT)
            issue_stage(g_h, smu + HS_OFF, x, smu + XT_OFF, b0, t + 1, true, tid);
    }
}

// ---------------- decoder: y = h @ W_dec^T  (f32x2 tiled GEMM) ----------------
__global__ void __launch_bounds__(256)
decoder_kernel(const float* __restrict__ h, const float* __restrict__ W,
               float* __restrict__ y) {
    __shared__ float HT[32 * 132];
    __shared__ float WT[32 * 68];
    const int tid = threadIdx.x;
    const int bt0 = blockIdx.x * 128;
    const int o0  = blockIdx.y * 64;
    const int rg = tid & 15;
    const int cg = tid >> 4;
    const int col0 = cg * 4;
    const int lrow = tid >> 1, lkh = (tid & 1) * 16;
    const int lcol = tid >> 2, lkw = (tid & 3) * 8;

    u64 acc[4][4];
#pragma unroll
    for (int i = 0; i < 4; i++)
#pragma unroll
        for (int c = 0; c < 4; c++) acc[i][c] = 0ull;

    for (int k0 = 0; k0 < NR; k0 += 32) {
        __syncthreads();
        const float4* hsrc =
            (const float4*)(h + (size_t)(bt0 + lrow) * NR + k0 + lkh);
#pragma unroll
        for (int j = 0; j < 4; j++) {
            float4 v = hsrc[j];
            int kk = lkh + 4 * j;
            HT[(kk + 0) * 132 + lrow] = v.x;
            HT[(kk + 1) * 132 + lrow] = v.y;
            HT[(kk + 2) * 132 + lrow] = v.z;
            HT[(kk + 3) * 132 + lrow] = v.w;
        }
        const float4* wsrc =
            (const float4*)(W + (size_t)(o0 + lcol) * NR + k0 + lkw);
#pragma unroll
        for (int j = 0; j < 2; j++) {
            float4 v = wsrc[j];
            int kk = lkw + 4 * j;
            WT[(kk + 0) * 68 + lcol] = v.x;
            WT[(kk + 1) * 68 + lcol] = v.y;
            WT[(kk + 2) * 68 + lcol] = v.z;
            WT[(kk + 3) * 68 + lcol] = v.w;
        }
        __syncthreads();
#pragma unroll 4
        for (int k = 0; k < 32; k++) {
            const u64* HTd = (const u64*)(HT + k * 132);
            u64 h0 = HTd[rg];
            u64 h1 = HTd[rg + 16];
            u64 h2 = HTd[rg + 32];
            u64 h3 = HTd[rg + 48];
            float4 wv = *(const float4*)(WT + k * 68 + col0);
            u64 w0 = pack2(wv.x, wv.x);
            u64 w1 = pack2(wv.y, wv.y);
            u64 w2 = pack2(wv.z, wv.z);
            u64 w3 = pack2(wv.w, wv.w);
            acc[0][0] = ffma2(h0, w0, acc[0][0]);
            acc[0][1] = ffma2(h0, w1, acc[0][1]);
            acc[0][2] = ffma2(h0, w2, acc[0][2]);
            acc[0][3] = ffma2(h0, w3, acc[0][3]);
            acc[1][0] = ffma2(h1, w0, acc[1][0]);
            acc[1][1] = ffma2(h1, w1, acc[1][1]);
            acc[1][2] = ffma2(h1, w2, acc[1][2]);
            acc[1][3] = ffma2(h1, w3, acc[1][3]);
            acc[2][0] = ffma2(h2, w0, acc[2][0]);
            acc[2][1] = ffma2(h2, w1, acc[2][1]);
            acc[2][2] = ffma2(h2, w2, acc[2][2]);
            acc[2][3] = ffma2(h2, w3, acc[2][3]);
            acc[3][0] = ffma2(h3, w0, acc[3][0]);
            acc[3][1] = ffma2(h3, w1, acc[3][1]);
            acc[3][2] = ffma2(h3, w2, acc[3][2]);
            acc[3][3] = ffma2(h3, w3, acc[3][3]);
        }
    }
#pragma unroll
    for (int i = 0; i < 4; i++) {
        int r = 2 * rg + 32 * i;
        float2 p0 = unpack2(acc[i][0]);
        float2 p1 = unpack2(acc[i][1]);
        float2 p2 = unpack2(acc[i][2]);
        float2 p3 = unpack2(acc[i][3]);
        float4 ra = make_float4(p0.x, p1.x, p2.x, p3.x);
        float4 rb = make_float4(p0.y, p1.y, p2.y, p3.y);
        *(float4*)(y + (size_t)(bt0 + r) * NOUT + o0 + col0) = ra;
        *(float4*)(y + (size_t)(bt0 + r + 1) * NOUT + o0 + col0) = rb;
    }
}

// ---------------- launch -------------------------------------------------------
extern "C" void kernel_launch(void* const* d_in, const int* in_sizes, int n_in,
                              void* d_out, int out_size) {
    const float* x          = (const float*)d_in[0];
    const float* init_state = (const float*)d_in[1];
    const float* W_enc      = (const float*)d_in[2];
    const float* W_wz       = (const float*)d_in[3];
    const float* W_uz       = (const float*)d_in[4];
    const float* W_wr       = (const float*)d_in[5];
    const float* W_ur       = (const float*)d_in[6];
    const float* W_wh       = (const float*)d_in[7];
    const float* W_uh       = (const float*)d_in[8];
    const float* W_dec      = (const float*)d_in[9];
    float* out = (float*)d_out;

    cudaFuncSetAttribute(rnn_persistent,
                         cudaFuncAttributeMaxDynamicSharedMemorySize, SMEM_TOTAL);

    rnn_persistent<<<PM * PN, NTH, SMEM_TOTAL>>>(
        x, init_state, W_enc, W_wz, W_uz, W_wr, W_ur, W_wh, W_uh, out);

    size_t hN = (size_t)BN * TT * NR;
    if ((size_t)out_size >= 2 * hN) {
        dim3 grid((BN * TT) / 128, NOUT / 64);
        decoder_kernel<<<grid, 256>>>(out, W_dec, out + hN);
    }

    reset_bar_kernel<<<1, 32>>>();
}